// round 5
// baseline (speedup 1.0000x reference)
#include <cuda_runtime.h>

// PowerFlowUnconstrainedSuperNodeGNN — GB300
//
// Algebraic restructure: message m_e = (concat(node_in[s_e], ef_e) @ Wm + b)*mask_e
// is linear, so segment_sum over receivers factors as:
//   agg[r] = S[r] @ Wm[0:34] + EF_agg[r] @ Wm[34:38] + cntf[r]*b
// with S[r] = sum_e mask_e * node_in[s_e]  (recomputed per layer),
// EF_agg/cntf layer-invariant (computed once).
// CSR built per call (deterministic work) -> atomic-free per-layer SpMM.

#define NN 100000
#define EE 3200000
#define HD 32
#define NL 3
#define NI 34          // node_in row: [V(2) | h(32)]

__device__ int    d_cnt[NN];
__device__ int    d_rs[NN + 1];
__device__ int    d_fill[NN];
__device__ int    d_src[EE];
__device__ float  d_msk[EE];
__device__ float  d_nin[(size_t)NN * NI];
__device__ float  d_S[(size_t)NN * NI];
__device__ float  d_h[(size_t)NN * HD];
__device__ float4 d_EF[NN];
__device__ float  d_cntf[NN];
__device__ float  d_pool[HD];
__device__ float  d_g[HD];

// ---------------------------------------------------------------- zero state
__global__ void k_zero(int n) {
    int i = blockIdx.x * blockDim.x + threadIdx.x;
    if (i < n) {
        d_cnt[i] = 0;
        d_fill[i] = 0;
        d_cntf[i] = 0.f;
        d_EF[i] = make_float4(0.f, 0.f, 0.f, 0.f);
    }
    if (i < HD) { d_pool[i] = 0.f; d_g[i] = 0.f; }
}

// ---------------------------------------------------------------- degree hist
__global__ void k_hist(const int* __restrict__ rcv, int e) {
    int i = blockIdx.x * blockDim.x + threadIdx.x;
    if (i < e) atomicAdd(&d_cnt[rcv[i]], 1);
}

// ------------------------------------------------- exclusive scan (1 block)
__global__ void k_scan(int n) {
    __shared__ int part[1024];
    int t = threadIdx.x;
    int chunk = (n + 1023) >> 10;
    int lo = t * chunk;
    int hi = min(lo + chunk, n);
    int s = 0;
    for (int i = lo; i < hi; i++) s += d_cnt[i];
    part[t] = s;
    __syncthreads();
    for (int off = 1; off < 1024; off <<= 1) {
        int v = (t >= off) ? part[t - off] : 0;
        __syncthreads();
        part[t] += v;
        __syncthreads();
    }
    int run = (t == 0) ? 0 : part[t - 1];
    for (int i = lo; i < hi; i++) { d_rs[i] = run; run += d_cnt[i]; }
    if (t == 1023) d_rs[n] = part[1023];
}

// -------------------------------------- scatter edges into CSR + EF/cnt aggs
__global__ void k_scatter(const int* __restrict__ snd, const int* __restrict__ rcv,
                          const float* __restrict__ ef, const float* __restrict__ mk,
                          int e) {
    int i = blockIdx.x * blockDim.x + threadIdx.x;
    if (i >= e) return;
    int r = rcv[i];
    int pos = d_rs[r] + atomicAdd(&d_fill[r], 1);
    d_src[pos] = snd[i];
    float m = mk[i];
    d_msk[pos] = m;
    const float4 f = *reinterpret_cast<const float4*>(ef + (size_t)i * 4);
    atomicAdd(&d_EF[r].x, m * f.x);
    atomicAdd(&d_EF[r].y, m * f.y);
    atomicAdd(&d_EF[r].z, m * f.z);
    atomicAdd(&d_EF[r].w, m * f.w);
    atomicAdd(&d_cntf[r], m);
}

// ----------------------------------------- init: V=[1,0], h0 = PQ@Win + bin
__global__ void k_init(const float* __restrict__ PQ, const float* __restrict__ Win,
                       const float* __restrict__ bin, int n) {
    int w = (blockIdx.x * blockDim.x + threadIdx.x) >> 5;
    int c = threadIdx.x & 31;
    if (w >= n) return;
    float p = __ldg(PQ + (size_t)w * 2);
    float q = __ldg(PQ + (size_t)w * 2 + 1);
    float hv = fmaf(p, __ldg(Win + c), fmaf(q, __ldg(Win + HD + c), __ldg(bin + c)));
    float* row = d_nin + (size_t)w * NI;
    if (c == 0) { row[0] = 1.f; row[1] = 0.f; }
    row[2 + c] = hv;
}

// -------------------- SpMM: S[r] = sum over incoming edges of mask*node_in[s]
// warp per row, lane per component (0..31) + lanes 0..1 handle comps 32..33
__global__ void k_spmm(int n) {
    int w = (blockIdx.x * blockDim.x + threadIdx.x) >> 5;
    int c = threadIdx.x & 31;
    if (w >= n) return;
    int s0 = d_rs[w], s1 = d_rs[w + 1];
    float a0 = 0.f, a1 = 0.f;
#pragma unroll 2
    for (int e = s0; e < s1; e++) {
        int src = __ldg(d_src + e);
        float m = __ldg(d_msk + e);
        const float* row = d_nin + (size_t)src * NI;
        a0 = fmaf(m, __ldg(row + c), a0);
        if (c < 2) a1 = fmaf(m, __ldg(row + 32 + c), a1);
    }
    float* out = d_S + (size_t)w * NI;
    out[c] = a0;
    if (c < 2) out[32 + c] = a1;
}

// ------- per-node: agg = S@Wm[0:34] + EF@Wm[34:38] + cntf*b; h=relu; pool sum
__global__ void k_msg(const float* __restrict__ Wm, const float* __restrict__ bm, int n) {
    __shared__ float bp[HD];
    int tid = threadIdx.x;
    if (tid < HD) bp[tid] = 0.f;
    __syncthreads();
    int w = (blockIdx.x * blockDim.x + tid) >> 5;
    int c = tid & 31;
    if (w < n) {
        const float* s = d_S + (size_t)w * NI;
        float a = 0.f;
#pragma unroll
        for (int k = 0; k < NI; k++) a = fmaf(__ldg(s + k), __ldg(Wm + k * HD + c), a);
        float4 f = d_EF[w];
        a = fmaf(f.x, __ldg(Wm + 34 * HD + c), a);
        a = fmaf(f.y, __ldg(Wm + 35 * HD + c), a);
        a = fmaf(f.z, __ldg(Wm + 36 * HD + c), a);
        a = fmaf(f.w, __ldg(Wm + 37 * HD + c), a);
        a = fmaf(__ldg(d_cntf + w), __ldg(bm + c), a);
        a = fmaxf(a, 0.f);
        d_h[(size_t)w * HD + c] = a;
        atomicAdd(&bp[c], a);
    }
    __syncthreads();
    if (tid < HD) atomicAdd(&d_pool[tid], bp[tid]);
}

// -------------------------------- global supernode update (1 block, 32 thr)
__global__ void k_gup(const float* __restrict__ Wg, const float* __restrict__ bg,
                      float inv_n) {
    __shared__ float gin[2 * HD];
    int t = threadIdx.x;
    gin[t] = d_g[t];
    gin[HD + t] = d_pool[t] * inv_n;
    __syncthreads();
    float a = __ldg(bg + t);
#pragma unroll
    for (int k = 0; k < 2 * HD; k++) a = fmaf(gin[k], __ldg(Wg + k * HD + t), a);
    a = fmaxf(a, 0.f);
    d_g[t] = a;
    d_pool[t] = 0.f;   // reset for next layer
}

// ----- per-node: h' = relu([h,g]@Wn+bn); V += h'@Wout+bout; node_in=[V,h']
__global__ void k_node(const float* __restrict__ Wn, const float* __restrict__ bn,
                       const float* __restrict__ Wo, const float* __restrict__ bo,
                       float* __restrict__ out, int n) {
    __shared__ float gg[HD];
    if (threadIdx.x < HD) gg[threadIdx.x] = d_g[threadIdx.x];
    __syncthreads();
    int w = (blockIdx.x * blockDim.x + threadIdx.x) >> 5;
    int c = threadIdx.x & 31;
    if (w >= n) return;
    const float* hrow = d_h + (size_t)w * HD;
    float a = __ldg(bn + c);
#pragma unroll
    for (int k = 0; k < HD; k++) a = fmaf(__ldg(hrow + k), __ldg(Wn + k * HD + c), a);
#pragma unroll
    for (int k = 0; k < HD; k++) a = fmaf(gg[k], __ldg(Wn + (HD + k) * HD + c), a);
    a = fmaxf(a, 0.f);
    float p0 = a * __ldg(Wo + c * 2);
    float p1 = a * __ldg(Wo + c * 2 + 1);
#pragma unroll
    for (int o = 16; o; o >>= 1) {
        p0 += __shfl_xor_sync(0xffffffffu, p0, o);
        p1 += __shfl_xor_sync(0xffffffffu, p1, o);
    }
    float* row = d_nin + (size_t)w * NI;
    float v0 = row[0] + p0 + __ldg(bo);
    float v1 = row[1] + p1 + __ldg(bo + 1);
    if (c == 0) {
        row[0] = v0;
        row[1] = v1;
        if (out) { out[(size_t)w * 2] = v0; out[(size_t)w * 2 + 1] = v1; }
    }
    row[2 + c] = a;
}

extern "C" void kernel_launch(void* const* d_in, const int* in_sizes, int n_in,
                              void* d_out, int out_size) {
    const float* PQ  = (const float*)d_in[0];
    const int*   snd = (const int*)  d_in[1];
    const int*   rcv = (const int*)  d_in[2];
    const float* ef  = (const float*)d_in[3];
    const float* mk  = (const float*)d_in[4];
    const float* Win = (const float*)d_in[5];
    const float* bin = (const float*)d_in[6];
    const float* Wm  = (const float*)d_in[7];   // (L,38,32)
    const float* bm  = (const float*)d_in[8];   // (L,32)
    const float* Wg  = (const float*)d_in[9];   // (L,64,32)
    const float* bg  = (const float*)d_in[10];
    const float* Wn  = (const float*)d_in[11];  // (L,64,32)
    const float* bn  = (const float*)d_in[12];
    const float* Wo  = (const float*)d_in[13];  // (L,32,2)
    const float* bo  = (const float*)d_in[14];  // (L,2)

    int n = in_sizes[0] / 2;
    int e = in_sizes[1];
    if (n > NN) n = NN;
    if (e > EE) e = EE;
    float* out = (float*)d_out;

    int nb_n = (n + 255) / 256;
    int nb_e = (e + 255) / 256;
    int nb_w = (int)(((long long)n * 32 + 255) / 256);

    k_zero<<<nb_n, 256>>>(n);
    k_hist<<<nb_e, 256>>>(rcv, e);
    k_scan<<<1, 1024>>>(n);
    k_scatter<<<nb_e, 256>>>(snd, rcv, ef, mk, e);
    k_init<<<nb_w, 256>>>(PQ, Win, bin, n);

    for (int l = 0; l < NL; l++) {
        k_spmm<<<nb_w, 256>>>(n);
        k_msg<<<nb_w, 256>>>(Wm + (size_t)l * 38 * HD, bm + (size_t)l * HD, n);
        k_gup<<<1, 32>>>(Wg + (size_t)l * 64 * HD, bg + (size_t)l * HD, 1.0f / (float)n);
        k_node<<<nb_w, 256>>>(Wn + (size_t)l * 64 * HD, bn + (size_t)l * HD,
                              Wo + (size_t)l * HD * 2, bo + (size_t)l * 2,
                              (l == NL - 1) ? out : nullptr, n);
    }
}

// round 8
// speedup vs baseline: 1.2891x; 1.2891x over previous
#include <cuda_runtime.h>

// PowerFlowUnconstrainedSuperNodeGNN — GB300, round 6
//
// msg is linear =>  agg[r] = sum_e m_e * (node_in[s_e] @ Wm) + (sum_e m_e ef_e) @ Wm_ef + (sum_e m_e) b
// Project node features FIRST (P = node_in @ Wm, aligned 128B rows), then the
// per-layer aggregation is a pure 32-wide gather-sum over a CSR built once per
// call. EF aggregate + masked degree are layer-invariant, computed atomic-free
// in CSR order. No float atomics anywhere except the 32-wide pool reduction.

#define NN 100000
#define EE 3200000
#define HD 32
#define NL 3
#define FULL 0xffffffffu

__device__ int    d_cnt[NN];
__device__ int    d_rs[NN + 1];
__device__ int    d_pos[EE];
__device__ int2   d_sm[EE];        // (src, mask bits) in CSR order
__device__ int    d_eid[EE];       // original edge id in CSR order
__device__ float  d_P[(size_t)NN * HD];   // projected node features (per layer)
__device__ float  d_h[(size_t)NN * HD];
__device__ float2 d_V[NN];
__device__ float4 d_EF[NN];
__device__ float  d_cntf[NN];
__device__ float  d_pool[HD];
__device__ float  d_g[HD];

// ---------------------------------------------------------------- zero state
__global__ void k_zero(int n) {
    int i = blockIdx.x * blockDim.x + threadIdx.x;
    if (i < n) d_cnt[i] = 0;
    if (i < HD) { d_pool[i] = 0.f; d_g[i] = 0.f; }
}

// ------------------------------------ histogram + per-edge slot in one pass
__global__ void k_histpos(const int* __restrict__ rcv, int e) {
    int i = blockIdx.x * blockDim.x + threadIdx.x;
    if (i < e) d_pos[i] = atomicAdd(&d_cnt[rcv[i]], 1);
}

// ------------------------------------------------- exclusive scan (1 block)
__global__ void k_scan(int n) {
    __shared__ int part[1024];
    int t = threadIdx.x;
    int chunk = (n + 1023) >> 10;
    int lo = t * chunk;
    int hi = min(lo + chunk, n);
    int s = 0;
    for (int i = lo; i < hi; i++) s += d_cnt[i];
    part[t] = s;
    __syncthreads();
    for (int off = 1; off < 1024; off <<= 1) {
        int v = (t >= off) ? part[t - off] : 0;
        __syncthreads();
        part[t] += v;
        __syncthreads();
    }
    int run = (t == 0) ? 0 : part[t - 1];
    for (int i = lo; i < hi; i++) { d_rs[i] = run; run += d_cnt[i]; }
    if (t == 1023) d_rs[n] = part[1023];
}

// --------------------------------- scatter edges into CSR slots (no atomics)
__global__ void k_scatter(const int* __restrict__ snd, const int* __restrict__ rcv,
                          const float* __restrict__ mk, int e) {
    int i = blockIdx.x * blockDim.x + threadIdx.x;
    if (i >= e) return;
    int p = d_rs[rcv[i]] + d_pos[i];
    d_sm[p] = make_int2(snd[i], __float_as_int(mk[i]));
    d_eid[p] = i;
}

// ---------------- layer-invariant EF aggregate + masked degree, atomic-free
__global__ void k_ef(const float* __restrict__ ef, int n) {
    int w = (blockIdx.x * blockDim.x + threadIdx.x) >> 5;
    int c = threadIdx.x & 31;
    if (w >= n) return;
    int s0 = d_rs[w], s1 = d_rs[w + 1];
    float ax = 0.f, ay = 0.f, az = 0.f, aw = 0.f, cnt = 0.f;
    for (int e = s0 + c; e < s1; e += 32) {
        float m = __int_as_float(d_sm[e].y);
        int id = d_eid[e];
        const float4 f = *reinterpret_cast<const float4*>(ef + (size_t)id * 4);
        ax = fmaf(m, f.x, ax); ay = fmaf(m, f.y, ay);
        az = fmaf(m, f.z, az); aw = fmaf(m, f.w, aw);
        cnt += m;
    }
#pragma unroll
    for (int o = 16; o; o >>= 1) {
        ax += __shfl_xor_sync(FULL, ax, o);
        ay += __shfl_xor_sync(FULL, ay, o);
        az += __shfl_xor_sync(FULL, az, o);
        aw += __shfl_xor_sync(FULL, aw, o);
        cnt += __shfl_xor_sync(FULL, cnt, o);
    }
    if (c == 0) { d_EF[w] = make_float4(ax, ay, az, aw); d_cntf[w] = cnt; }
}

// --------------- init: V=(1,0), h0 = PQ@Win + bin, P0 = [V0,h0]@Wm[0][0:34]
__global__ void k_init(const float* __restrict__ PQ, const float* __restrict__ Win,
                       const float* __restrict__ bin, const float* __restrict__ Wm0,
                       int n) {
    int w = (blockIdx.x * blockDim.x + threadIdx.x) >> 5;
    int c = threadIdx.x & 31;
    if (w >= n) return;
    float p = __ldg(PQ + (size_t)w * 2);
    float q = __ldg(PQ + (size_t)w * 2 + 1);
    float hv = fmaf(p, __ldg(Win + c), fmaf(q, __ldg(Win + HD + c), __ldg(bin + c)));
    float pacc = __ldg(Wm0 + c);                 // V0 = (1, 0): only row 0 counts
#pragma unroll
    for (int k = 0; k < HD; k++)
        pacc = fmaf(__shfl_sync(FULL, hv, k), __ldg(Wm0 + (2 + k) * HD + c), pacc);
    d_P[(size_t)w * HD + c] = pacc;
    if (c == 0) d_V[w] = make_float2(1.f, 0.f);
}

// ------ SpMM + epilogue: h[r]=relu( sum m*P[s] + EF@Wm_ef + cntf*b ); pool
__global__ void __launch_bounds__(256) k_spmm(const float* __restrict__ Wt,
                                              const float* __restrict__ bm, int n) {
    __shared__ float bp[HD];
    int tid = threadIdx.x;
    if (tid < HD) bp[tid] = 0.f;
    __syncthreads();
    int w = (blockIdx.x * blockDim.x + tid) >> 5;
    int c = tid & 31;
    if (w < n) {
        int s0 = d_rs[w], s1 = d_rs[w + 1];
        float acc = 0.f;
        int base = s0;
        for (; base + 32 <= s1; base += 32) {
            int2 sm = d_sm[base + c];
#pragma unroll
            for (int j = 0; j < 32; j++) {
                int   src = __shfl_sync(FULL, sm.x, j);
                float m   = __int_as_float(__shfl_sync(FULL, sm.y, j));
                acc = fmaf(m, __ldg(d_P + (size_t)src * HD + c), acc);
            }
        }
        if (base < s1) {
            int idx = base + c;
            int2 sm = (idx < s1) ? d_sm[idx] : make_int2(0, 0);
            int lim = s1 - base;
#pragma unroll 4
            for (int j = 0; j < lim; j++) {
                int   src = __shfl_sync(FULL, sm.x, j);
                float m   = __int_as_float(__shfl_sync(FULL, sm.y, j));
                acc = fmaf(m, __ldg(d_P + (size_t)src * HD + c), acc);
            }
        }
        const float4 f = d_EF[w];
        acc = fmaf(f.x, __ldg(Wt + c),          acc);
        acc = fmaf(f.y, __ldg(Wt + HD + c),     acc);
        acc = fmaf(f.z, __ldg(Wt + 2 * HD + c), acc);
        acc = fmaf(f.w, __ldg(Wt + 3 * HD + c), acc);
        acc = fmaf(__ldg(d_cntf + w), __ldg(bm + c), acc);
        acc = fmaxf(acc, 0.f);
        d_h[(size_t)w * HD + c] = acc;
        atomicAdd(&bp[c], acc);
    }
    __syncthreads();
    if (tid < HD) atomicAdd(&d_pool[tid], bp[tid]);
}

// -------------------------------- global supernode update (1 block, 32 thr)
__global__ void k_gup(const float* __restrict__ Wg, const float* __restrict__ bg,
                      float inv_n) {
    __shared__ float gin[2 * HD];
    int t = threadIdx.x;
    gin[t] = d_g[t];
    gin[HD + t] = d_pool[t] * inv_n;
    __syncthreads();
    float a = __ldg(bg + t);
#pragma unroll
    for (int k = 0; k < 2 * HD; k++) a = fmaf(gin[k], __ldg(Wg + k * HD + t), a);
    a = fmaxf(a, 0.f);
    d_g[t] = a;
    d_pool[t] = 0.f;   // reset for next layer
}

// --- node update: h'=relu([h,g]@Wn+bn); V+=h'@Wo+bo; P_next=[V',h']@Wm_next
__global__ void k_node(const float* __restrict__ Wn, const float* __restrict__ bn,
                       const float* __restrict__ Wo, const float* __restrict__ bo,
                       const float* __restrict__ Wm_next,
                       float* __restrict__ out, int n) {
    __shared__ float gg[HD];
    if (threadIdx.x < HD) gg[threadIdx.x] = d_g[threadIdx.x];
    __syncthreads();
    int w = (blockIdx.x * blockDim.x + threadIdx.x) >> 5;
    int c = threadIdx.x & 31;
    if (w >= n) return;
    const float* hrow = d_h + (size_t)w * HD;
    float a = __ldg(bn + c);
#pragma unroll
    for (int k = 0; k < HD; k++) a = fmaf(__ldg(hrow + k), __ldg(Wn + k * HD + c), a);
#pragma unroll
    for (int k = 0; k < HD; k++) a = fmaf(gg[k], __ldg(Wn + (HD + k) * HD + c), a);
    a = fmaxf(a, 0.f);
    float p0 = a * __ldg(Wo + c * 2);
    float p1 = a * __ldg(Wo + c * 2 + 1);
#pragma unroll
    for (int o = 16; o; o >>= 1) {
        p0 += __shfl_xor_sync(FULL, p0, o);
        p1 += __shfl_xor_sync(FULL, p1, o);
    }
    float2 V = d_V[w];
    float v0 = V.x + p0 + __ldg(bo);
    float v1 = V.y + p1 + __ldg(bo + 1);
    if (c == 0) d_V[w] = make_float2(v0, v1);
    if (out) {
        if (c == 0) reinterpret_cast<float2*>(out)[w] = make_float2(v0, v1);
    } else {
        float pacc = fmaf(v0, __ldg(Wm_next + c),
                     fmaf(v1, __ldg(Wm_next + HD + c), 0.f));
#pragma unroll
        for (int k = 0; k < HD; k++)
            pacc = fmaf(__shfl_sync(FULL, a, k), __ldg(Wm_next + (2 + k) * HD + c), pacc);
        d_P[(size_t)w * HD + c] = pacc;
    }
}

extern "C" void kernel_launch(void* const* d_in, const int* in_sizes, int n_in,
                              void* d_out, int out_size) {
    const float* PQ  = (const float*)d_in[0];
    const int*   snd = (const int*)  d_in[1];
    const int*   rcv = (const int*)  d_in[2];
    const float* ef  = (const float*)d_in[3];
    const float* mk  = (const float*)d_in[4];
    const float* Win = (const float*)d_in[5];
    const float* bin = (const float*)d_in[6];
    const float* Wm  = (const float*)d_in[7];   // (L,38,32)
    const float* bm  = (const float*)d_in[8];   // (L,32)
    const float* Wg  = (const float*)d_in[9];   // (L,64,32)
    const float* bg  = (const float*)d_in[10];
    const float* Wn  = (const float*)d_in[11];  // (L,64,32)
    const float* bn  = (const float*)d_in[12];
    const float* Wo  = (const float*)d_in[13];  // (L,32,2)
    const float* bo  = (const float*)d_in[14];  // (L,2)

    int n = in_sizes[0] / 2;
    int e = in_sizes[1];
    if (n > NN) n = NN;
    if (e > EE) e = EE;
    float* out = (float*)d_out;

    int nb_n = (n + 255) / 256;
    int nb_e = (e + 255) / 256;
    int nb_w = (int)(((long long)n * 32 + 255) / 256);

    k_zero<<<nb_n, 256>>>(n);
    k_histpos<<<nb_e, 256>>>(rcv, e);
    k_scan<<<1, 1024>>>(n);
    k_scatter<<<nb_e, 256>>>(snd, rcv, mk, e);
    k_ef<<<nb_w, 256>>>(ef, n);
    k_init<<<nb_w, 256>>>(PQ, Win, bin, Wm, n);

    for (int l = 0; l < NL; l++) {
        k_spmm<<<nb_w, 256>>>(Wm + (size_t)l * 38 * HD + 34 * HD,
                              bm + (size_t)l * HD, n);
        k_gup<<<1, 32>>>(Wg + (size_t)l * 64 * HD, bg + (size_t)l * HD,
                         1.0f / (float)n);
        k_node<<<nb_w, 256>>>(Wn + (size_t)l * 64 * HD, bn + (size_t)l * HD,
                              Wo + (size_t)l * HD * 2, bo + (size_t)l * 2,
                              (l < NL - 1) ? (Wm + (size_t)(l + 1) * 38 * HD) : nullptr,
                              (l == NL - 1) ? out : nullptr, n);
    }
}